// round 8
// baseline (speedup 1.0000x reference)
#include <cuda_runtime.h>
#include <cstdint>

// ---------------------------------------------------------------------------
// GAT hierarchical 2-layer. R8: single-task attention blocks (R6 form),
// layer-1 logits fused into attn128 (elogN/elogS side outputs), attn512
// reduced to softmax+aggregate, main GEMMs re-tiled 32x32 for parallelism.
// ---------------------------------------------------------------------------

// scratch layout (floats)
static constexpr size_t OFF_Y1 = 0;                        // [10240,512]
static constexpr size_t OFF_Y0 = OFF_Y1 + 10240ull * 512;  // [1024,512]
static constexpr size_t OFF_U  = OFF_Y0 + 1024ull * 512;   // [1024,2048]
static constexpr size_t OFF_H  = OFF_U  + 1024ull * 2048;  // [1024,512]
static constexpr size_t OFF_P0 = OFF_H  + 1024ull * 512;   // P0s[512],P0n[512]
static constexpr size_t OFF_Q  = OFF_P0 + 1024;            // Qs[2048],Qn[2048]
static constexpr size_t OFF_N  = OFF_Q  + 4096;            // N[4][512][128]
static constexpr size_t OFF_EN = OFF_N  + 4ull * 512 * 128;// elogN [10240,4]
static constexpr size_t OFF_ES = OFF_EN + 10240ull * 4;    // elogS [1024,4]
static constexpr size_t SCRATCH_FLOATS = OFF_ES + 1024ull * 4;

__device__ float g_scratch[SCRATCH_FLOATS];

static __device__ __forceinline__ float4 ldg4(const float* p) {
    return __ldg((const float4*)p);
}
static __device__ __forceinline__ float dot4(float4 a, float4 b, float acc) {
    acc = fmaf(a.x, b.x, acc);
    acc = fmaf(a.y, b.y, acc);
    acc = fmaf(a.z, b.z, acc);
    acc = fmaf(a.w, b.w, acc);
    return acc;
}
static __device__ __forceinline__ uint32_t smem_u32(const void* p) {
    return (uint32_t)__cvta_generic_to_shared(p);
}
static __device__ __forceinline__ void mbar_init(uint32_t mbar, uint32_t cnt) {
    asm volatile("mbarrier.init.shared.b64 [%0], %1;" :: "r"(mbar), "r"(cnt) : "memory");
}
static __device__ __forceinline__ void mbar_expect_tx(uint32_t mbar, uint32_t bytes) {
    asm volatile("mbarrier.arrive.expect_tx.shared.b64 _, [%0], %1;"
                 :: "r"(mbar), "r"(bytes) : "memory");
}
static __device__ __forceinline__ void bulk_g2s(uint32_t dst, const void* src,
                                                uint32_t bytes, uint32_t mbar) {
    asm volatile("cp.async.bulk.shared::cluster.global.mbarrier::complete_tx::bytes "
                 "[%0], [%1], %2, [%3];"
                 :: "r"(dst), "l"(src), "r"(bytes), "r"(mbar) : "memory");
}
static __device__ __forceinline__ void mbar_wait(uint32_t mbar, uint32_t parity) {
    asm volatile(
        "{\n\t.reg .pred P;\n"
        "W_%=:\n\t"
        "mbarrier.try_wait.parity.shared.b64 P, [%0], %1;\n\t"
        "@P bra D_%=;\n\t"
        "bra W_%=;\n"
        "D_%=:\n\t}"
        :: "r"(mbar), "r"(parity) : "memory");
}
static __device__ __forceinline__ float4 lds4(const float* p) {
    float4 v;
    asm volatile("ld.shared.v4.f32 {%0,%1,%2,%3}, [%4];"
                 : "=f"(v.x), "=f"(v.y), "=f"(v.z), "=f"(v.w)
                 : "r"(smem_u32(p)));
    return v;
}

// ---------------------------------------------------------------------------
// prepN (32x32 tiles), unchanged from R6.
// ---------------------------------------------------------------------------
__global__ __launch_bounds__(256)
void prepN_kernel(const float* __restrict__ W0, const float* __restrict__ W1,
                  float* __restrict__ Nmat)
{
    const int z = blockIdx.z;
    const int hp = z >> 2, h = z & 3;
    const float* A = W0 + h * 128;
    const float* B = W1 + (size_t)(h * 128) * 512 + hp * 128;
    float* C = Nmat + (size_t)hp * 65536 + (size_t)(h * 128) * 128;

    const int M0 = blockIdx.y * 32;
    const int N0 = blockIdx.x * 32;
    const int tx = threadIdx.x & 15;
    const int ty = threadIdx.x >> 4;
    const int tid = threadIdx.x;

    __shared__ float As[16][32];
    __shared__ float Bs[16][32];

    float acc[2][2] = {{0.f, 0.f}, {0.f, 0.f}};

    for (int k0 = 0; k0 < 128; k0 += 16) {
        if (tid < 128) {
            int r = tid >> 2, c4 = (tid & 3) * 4;
            float4 av = *(const float4*)(A + (size_t)(M0 + r) * 512 + k0 + c4);
            As[c4 + 0][r] = av.x;
            As[c4 + 1][r] = av.y;
            As[c4 + 2][r] = av.z;
            As[c4 + 3][r] = av.w;
        } else {
            int t = tid - 128;
            int r = t >> 3, c4 = (t & 7) * 4;
            float4 bv = *(const float4*)(B + (size_t)(k0 + r) * 512 + N0 + c4);
            *(float4*)&Bs[r][c4] = bv;
        }
        __syncthreads();
        #pragma unroll
        for (int k = 0; k < 16; k++) {
            float a0 = As[k][ty * 2], a1 = As[k][ty * 2 + 1];
            float b0 = Bs[k][tx * 2], b1 = Bs[k][tx * 2 + 1];
            acc[0][0] = fmaf(a0, b0, acc[0][0]);
            acc[0][1] = fmaf(a0, b1, acc[0][1]);
            acc[1][0] = fmaf(a1, b0, acc[1][0]);
            acc[1][1] = fmaf(a1, b1, acc[1][1]);
        }
        __syncthreads();
    }
    #pragma unroll
    for (int i = 0; i < 2; i++)
        #pragma unroll
        for (int j = 0; j < 2; j++)
            C[(size_t)(M0 + ty * 2 + i) * 128 + N0 + tx * 2 + j] = acc[i][j];
}

// ---------------------------------------------------------------------------
// prepQP, unchanged from R6.
// ---------------------------------------------------------------------------
__global__ __launch_bounds__(128)
void prepQP_kernel(const float* __restrict__ Nmat,
                   const float* __restrict__ a1s, const float* __restrict__ a1n,
                   const float* __restrict__ W0,
                   const float* __restrict__ a0s, const float* __restrict__ a0n,
                   float* __restrict__ Q, float* __restrict__ P0)
{
    const int b = blockIdx.x;
    const int tid = threadIdx.x;
    if (b < 16) {
        const int hp = b >> 2, h = b & 3;
        __shared__ float sa1s[128], sa1n[128];
        sa1s[tid] = a1s[hp * 128 + tid];
        sa1n[tid] = a1n[hp * 128 + tid];
        __syncthreads();
        const float* nrow = Nmat + (size_t)hp * 65536 + (size_t)(h * 128 + tid) * 128;
        float s = 0.f, n = 0.f;
        #pragma unroll 4
        for (int d = 0; d < 128; d++) {
            float nv = nrow[d];
            s = fmaf(nv, sa1s[d], s);
            n = fmaf(nv, sa1n[d], n);
        }
        Q[hp * 512 + h * 128 + tid] = s;
        Q[2048 + hp * 512 + h * 128 + tid] = n;
    } else {
        const int t = (b - 16) * 128 + tid;
        const int h = t >> 7, f = t & 127;
        const float* wrow = W0 + (size_t)f * 512 + h * 128;
        const float* as = a0s + h * 128;
        const float* an = a0n + h * 128;
        float s = 0.f, n = 0.f;
        #pragma unroll 4
        for (int d = 0; d < 128; d++) {
            float wv = wrow[d];
            s = fmaf(wv, as[d], s);
            n = fmaf(wv, an[d], n);
        }
        P0[t] = s;
        P0[512 + t] = n;
    }
}

// ---------------------------------------------------------------------------
// 32x32-tile fp32 GEMM, BK=16, 256 threads, 2x2/thread, reg double-buffer.
// Batched via blockIdx.z element offsets.
// ---------------------------------------------------------------------------
__global__ __launch_bounds__(256)
void gemm32_kernel(const float* __restrict__ A, const float* __restrict__ B,
                   float* __restrict__ C,
                   int K, int lda, int ldb, int ldc,
                   int offA, int offB, int offC)
{
    A += (size_t)blockIdx.z * offA;
    B += (size_t)blockIdx.z * offB;
    C += (size_t)blockIdx.z * offC;

    const int M0 = blockIdx.y * 32;
    const int N0 = blockIdx.x * 32;
    const int tid = threadIdx.x;
    const int tx = tid & 15;
    const int ty = tid >> 4;

    __shared__ float As[16][32];
    __shared__ float Bs[16][32];

    const bool isA = tid < 128;
    const int ar = tid >> 2, ac = (tid & 3) * 4;             // A: 32 rows x 16 cols
    const int brt = (tid - 128) >> 3, bct = ((tid - 128) & 7) * 4; // B: 16 x 32

    float acc[2][2] = {{0.f, 0.f}, {0.f, 0.f}};
    const int nt = K >> 4;

    float4 v;
    if (isA) v = *(const float4*)(A + (size_t)(M0 + ar) * lda + ac);
    else     v = *(const float4*)(B + (size_t)brt * ldb + N0 + bct);

    for (int i = 0; i < nt; i++) {
        if (isA) {
            As[ac + 0][ar] = v.x;
            As[ac + 1][ar] = v.y;
            As[ac + 2][ar] = v.z;
            As[ac + 3][ar] = v.w;
        } else {
            *(float4*)&Bs[brt][bct] = v;
        }
        __syncthreads();

        if (i + 1 < nt) {
            int k0 = (i + 1) << 4;
            if (isA) v = *(const float4*)(A + (size_t)(M0 + ar) * lda + k0 + ac);
            else     v = *(const float4*)(B + (size_t)(k0 + brt) * ldb + N0 + bct);
        }

        #pragma unroll
        for (int k = 0; k < 16; k++) {
            float a0 = As[k][ty * 2], a1 = As[k][ty * 2 + 1];
            float b0 = Bs[k][tx * 2], b1 = Bs[k][tx * 2 + 1];
            acc[0][0] = fmaf(a0, b0, acc[0][0]);
            acc[0][1] = fmaf(a0, b1, acc[0][1]);
            acc[1][0] = fmaf(a1, b0, acc[1][0]);
            acc[1][1] = fmaf(a1, b1, acc[1][1]);
        }
        __syncthreads();
    }
    #pragma unroll
    for (int i = 0; i < 2; i++)
        #pragma unroll
        for (int j = 0; j < 2; j++)
            C[(size_t)(M0 + ty * 2 + i) * ldc + N0 + tx * 2 + j] = acc[i][j];
}

// ---------------------------------------------------------------------------
// F=128 attention (both levels), one task per block, + fused layer-1 logit
// partials: elogN[t,hp] = y1[t] . Qn[hp] (big), elogS[g,hp] = y0[g] . Qs[hp].
// ---------------------------------------------------------------------------
__global__ __launch_bounds__(128)
void attn128_kernel(const float* __restrict__ h0, const float* __restrict__ h1,
                    const float* __restrict__ h2,
                    const float* __restrict__ Ws, const float* __restrict__ Wn,
                    const float* __restrict__ Q,
                    float* __restrict__ y1, float* __restrict__ y0,
                    float* __restrict__ elogN, float* __restrict__ elogS, int G1)
{
    __shared__ float sxn[25 * 128];
    __shared__ float slog[26 * 4];
    __shared__ float salpha[25 * 4];
    __shared__ float sred[4][4];
    __shared__ uint64_t mbar_s;

    const int b = blockIdx.x;
    const bool big = b < G1;
    const int g = big ? b : b - G1;
    const int E = big ? 25 : 10;
    const float* gxn = big ? (h2 + (size_t)g * 25 * 128) : (h1 + (size_t)g * 10 * 128);
    const float* gxs = big ? (h1 + (size_t)g * 128) : (h0 + (size_t)g * 128);
    float* gy = (big ? y1 : y0) + (size_t)g * 512;
    float* eout = (big ? elogN : elogS) + (size_t)g * 4;

    const int tid  = threadIdx.x;
    const int w    = tid >> 5;
    const int lane = tid & 31;
    const uint32_t mbar = smem_u32(&mbar_s);

    if (tid == 0) {
        mbar_init(mbar, 1);
        asm volatile("fence.proxy.async.shared::cta;" ::: "memory");
    }
    __syncthreads();
    if (tid == 0) {
        mbar_expect_tx(mbar, (uint32_t)(E * 128 * 4));
        bulk_g2s(smem_u32(sxn), gxn, (uint32_t)(E * 128 * 4), mbar);
    }

    const int hh = lane & 3;
    const int s  = lane >> 2;
    float4 wq[4];
    #pragma unroll
    for (int j = 0; j < 4; j++) wq[j] = ldg4(Wn + hh * 128 + 4 * (s + 8 * j));

    // layer-1 weight slice for the elog side-output
    const float* qb = Q + (big ? 2048 : 0);
    float qv[4][4];
    #pragma unroll
    for (int hp = 0; hp < 4; hp++)
        #pragma unroll
        for (int q = 0; q < 4; q++)
            qv[hp][q] = __ldg(qb + hp * 512 + q * 128 + tid);

    if (w == 0) {  // self logit from global
        float acc = 0.f;
        #pragma unroll
        for (int j = 0; j < 4; j++)
            acc = dot4(ldg4(gxs + 4 * (s + 8 * j)),
                       ldg4(Ws + hh * 128 + 4 * (s + 8 * j)), acc);
        acc += __shfl_xor_sync(0xffffffffu, acc, 4);
        acc += __shfl_xor_sync(0xffffffffu, acc, 8);
        acc += __shfl_xor_sync(0xffffffffu, acc, 16);
        if (lane < 4) slog[E * 4 + lane] = acc;
    }

    mbar_wait(mbar, 0);

    for (int e = w; e < E; e += 4) {
        const float* xp = &sxn[e * 128];
        float acc = 0.f;
        #pragma unroll
        for (int j = 0; j < 4; j++)
            acc = dot4(lds4(xp + 4 * (s + 8 * j)), wq[j], acc);
        acc += __shfl_xor_sync(0xffffffffu, acc, 4);
        acc += __shfl_xor_sync(0xffffffffu, acc, 8);
        acc += __shfl_xor_sync(0xffffffffu, acc, 16);
        if (lane < 4) slog[e * 4 + lane] = acc;
    }
    __syncthreads();

    {   // softmax per head
        float es = slog[E * 4 + w];
        float v;
        if (lane < E) {
            float l = es + slog[lane * 4 + w];
            v = (l >= 0.f) ? l : 0.2f * l;
        } else {
            v = -3.4e38f;
        }
        float m = v;
        #pragma unroll
        for (int o = 16; o; o >>= 1) m = fmaxf(m, __shfl_xor_sync(0xffffffffu, m, o));
        float p = (lane < E) ? __expf(v - m) : 0.f;
        float sum = p;
        #pragma unroll
        for (int o = 16; o; o >>= 1) sum += __shfl_xor_sync(0xffffffffu, sum, o);
        if (lane < E) salpha[lane * 4 + w] = p / sum;
    }
    __syncthreads();

    // aggregate; thread covers column tid; acc[q] = y[q*128+tid]
    float acc[4] = {0.f, 0.f, 0.f, 0.f};
    for (int e = 0; e < E; e++) {
        float val = sxn[e * 128 + tid];
        #pragma unroll
        for (int q = 0; q < 4; q++) acc[q] = fmaf(salpha[e * 4 + q], val, acc[q]);
    }
    #pragma unroll
    for (int q = 0; q < 4; q++) gy[q * 128 + tid] = acc[q];

    // fused layer-1 logit partials: p[hp] = sum_f y[f] * Q[hp][f]
    float p[4];
    #pragma unroll
    for (int hp = 0; hp < 4; hp++) {
        float t = 0.f;
        #pragma unroll
        for (int q = 0; q < 4; q++) t = fmaf(acc[q], qv[hp][q], t);
        #pragma unroll
        for (int o = 16; o; o >>= 1) t += __shfl_xor_sync(0xffffffffu, t, o);
        p[hp] = t;
    }
    if (lane == 0) {
        #pragma unroll
        for (int hp = 0; hp < 4; hp++) sred[w][hp] = p[hp];
    }
    __syncthreads();
    if (tid < 4)
        eout[tid] = sred[0][tid] + sred[1][tid] + sred[2][tid] + sred[3][tid];
}

// ---------------------------------------------------------------------------
// F=512, E=10 layer-1: logits precomputed (elogN/elogS); TMA + softmax +
// aggregate only. One task per block, grid 1024.
// ---------------------------------------------------------------------------
__global__ __launch_bounds__(128)
void attn512_kernel(const float* __restrict__ xn,
                    const float* __restrict__ elogS, const float* __restrict__ elogN,
                    float* __restrict__ y)
{
    constexpr int E = 10, F = 512;
    __shared__ float sxn[E * F];
    __shared__ float salpha[E * 4];
    __shared__ uint64_t mbar_s;

    const int g    = blockIdx.x;
    const int tid  = threadIdx.x;
    const int w    = tid >> 5;
    const int lane = tid & 31;
    const uint32_t mbar = smem_u32(&mbar_s);
    const float* gxn = xn + (size_t)g * E * F;

    if (tid == 0) {
        mbar_init(mbar, 1);
        asm volatile("fence.proxy.async.shared::cta;" ::: "memory");
    }
    __syncthreads();
    if (tid == 0) {
        mbar_expect_tx(mbar, E * F * 4);
        bulk_g2s(smem_u32(sxn), gxn, E * F * 4, mbar);
    }

    {   // softmax per head from precomputed logits (warp w = head)
        float es = __ldg(elogS + g * 4 + w);
        float v;
        if (lane < E) {
            float l = es + __ldg(elogN + (size_t)(g * 10 + lane) * 4 + w);
            v = (l >= 0.f) ? l : 0.2f * l;
        } else {
            v = -3.4e38f;
        }
        float m = v;
        #pragma unroll
        for (int o = 16; o; o >>= 1) m = fmaxf(m, __shfl_xor_sync(0xffffffffu, m, o));
        float p = (lane < E) ? __expf(v - m) : 0.f;
        float sum = p;
        #pragma unroll
        for (int o = 16; o; o >>= 1) sum += __shfl_xor_sync(0xffffffffu, sum, o);
        if (lane < E) salpha[lane * 4 + w] = p / sum;
    }

    mbar_wait(mbar, 0);
    __syncthreads();

    float acc[4][4];
    #pragma unroll
    for (int c = 0; c < 4; c++)
        #pragma unroll
        for (int q = 0; q < 4; q++) acc[c][q] = 0.f;
    for (int e = 0; e < E; e++) {
        float al[4];
        #pragma unroll
        for (int q = 0; q < 4; q++) al[q] = salpha[e * 4 + q];
        #pragma unroll
        for (int c = 0; c < 4; c++) {
            float val = sxn[e * F + c * 128 + tid];
            #pragma unroll
            for (int q = 0; q < 4; q++) acc[c][q] = fmaf(al[q], val, acc[c][q]);
        }
    }
    float* gy = y + (size_t)g * (4 * F);
    #pragma unroll
    for (int q = 0; q < 4; q++)
        #pragma unroll
        for (int c = 0; c < 4; c++)
            gy[q * F + c * 128 + tid] = acc[c][q];
}

// ---------------------------------------------------------------------------
extern "C" void kernel_launch(void* const* d_in, const int* in_sizes, int n_in,
                              void* d_out, int out_size)
{
    const float* h0  = (const float*)d_in[0];
    const float* h1  = (const float*)d_in[1];
    const float* h2  = (const float*)d_in[2];
    const float* W0  = (const float*)d_in[3];
    const float* a0s = (const float*)d_in[4];
    const float* a0n = (const float*)d_in[5];
    const float* W1  = (const float*)d_in[6];
    const float* a1s = (const float*)d_in[7];
    const float* a1n = (const float*)d_in[8];
    const float* Wfc = (const float*)d_in[9];
    float* out = (float*)d_out;

    float* scr = nullptr;
    cudaGetSymbolAddress((void**)&scr, g_scratch);
    float* y1    = scr + OFF_Y1;
    float* y0    = scr + OFF_Y0;
    float* u     = scr + OFF_U;
    float* hs0   = scr + OFF_H;
    float* P0    = scr + OFF_P0;
    float* Q     = scr + OFF_Q;
    float* Nmat  = scr + OFF_N;
    float* elogN = scr + OFF_EN;
    float* elogS = scr + OFF_ES;

    prepN_kernel<<<dim3(4, 4, 16), 256>>>(W0, W1, Nmat);
    prepQP_kernel<<<20, 128>>>(Nmat, a1s, a1n, W0, a0s, a0n, Q, P0);

    // both F=128 attentions + fused layer-1 logits
    attn128_kernel<<<10240 + 1024, 128>>>(h0, h1, h2, P0, P0 + 512, Q,
                                          y1, y0, elogN, elogS, 10240);

    // layer-1 softmax + aggregation only
    attn512_kernel<<<1024, 128>>>(y1, elogS, elogN, u);

    // hs0[g, hp*128+d'] = u[g,hp,:] @ N[hp]
    gemm32_kernel<<<dim3(4, 32, 4), 256>>>(u, Nmat, hs0, 512, 2048, 128, 512,
                                           512, 512 * 128, 128);
    // out = hs0 @ Wfc
    gemm32_kernel<<<dim3(8, 32, 1), 256>>>(hs0, Wfc, out, 512, 512, 256, 256,
                                           0, 0, 0);
}

// round 9
// speedup vs baseline: 1.0756x; 1.0756x over previous
#include <cuda_runtime.h>
#include <cstdint>

// ---------------------------------------------------------------------------
// GAT hierarchical 2-layer. R9 = R8 with two fixes: attn128 dispatches to a
// compile-time-E body (restores loop unrolling / LDS MLP lost in R8), and the
// main GEMMs revert to the proven 64x64 double-buffered tile. Keeps the
// layer-1 logit hoist (elogN/elogS) and the slim attn512.
// ---------------------------------------------------------------------------

// scratch layout (floats)
static constexpr size_t OFF_Y1 = 0;                        // [10240,512]
static constexpr size_t OFF_Y0 = OFF_Y1 + 10240ull * 512;  // [1024,512]
static constexpr size_t OFF_U  = OFF_Y0 + 1024ull * 512;   // [1024,2048]
static constexpr size_t OFF_H  = OFF_U  + 1024ull * 2048;  // [1024,512]
static constexpr size_t OFF_P0 = OFF_H  + 1024ull * 512;   // P0s[512],P0n[512]
static constexpr size_t OFF_Q  = OFF_P0 + 1024;            // Qs[2048],Qn[2048]
static constexpr size_t OFF_N  = OFF_Q  + 4096;            // N[4][512][128]
static constexpr size_t OFF_EN = OFF_N  + 4ull * 512 * 128;// elogN [10240,4]
static constexpr size_t OFF_ES = OFF_EN + 10240ull * 4;    // elogS [1024,4]
static constexpr size_t SCRATCH_FLOATS = OFF_ES + 1024ull * 4;

__device__ float g_scratch[SCRATCH_FLOATS];

static __device__ __forceinline__ float4 ldg4(const float* p) {
    return __ldg((const float4*)p);
}
static __device__ __forceinline__ float dot4(float4 a, float4 b, float acc) {
    acc = fmaf(a.x, b.x, acc);
    acc = fmaf(a.y, b.y, acc);
    acc = fmaf(a.z, b.z, acc);
    acc = fmaf(a.w, b.w, acc);
    return acc;
}
static __device__ __forceinline__ uint32_t smem_u32(const void* p) {
    return (uint32_t)__cvta_generic_to_shared(p);
}
static __device__ __forceinline__ void mbar_init(uint32_t mbar, uint32_t cnt) {
    asm volatile("mbarrier.init.shared.b64 [%0], %1;" :: "r"(mbar), "r"(cnt) : "memory");
}
static __device__ __forceinline__ void mbar_expect_tx(uint32_t mbar, uint32_t bytes) {
    asm volatile("mbarrier.arrive.expect_tx.shared.b64 _, [%0], %1;"
                 :: "r"(mbar), "r"(bytes) : "memory");
}
static __device__ __forceinline__ void bulk_g2s(uint32_t dst, const void* src,
                                                uint32_t bytes, uint32_t mbar) {
    asm volatile("cp.async.bulk.shared::cluster.global.mbarrier::complete_tx::bytes "
                 "[%0], [%1], %2, [%3];"
                 :: "r"(dst), "l"(src), "r"(bytes), "r"(mbar) : "memory");
}
static __device__ __forceinline__ void mbar_wait(uint32_t mbar, uint32_t parity) {
    asm volatile(
        "{\n\t.reg .pred P;\n"
        "W_%=:\n\t"
        "mbarrier.try_wait.parity.shared.b64 P, [%0], %1;\n\t"
        "@P bra D_%=;\n\t"
        "bra W_%=;\n"
        "D_%=:\n\t}"
        :: "r"(mbar), "r"(parity) : "memory");
}
static __device__ __forceinline__ float4 lds4(const float* p) {
    float4 v;
    asm volatile("ld.shared.v4.f32 {%0,%1,%2,%3}, [%4];"
                 : "=f"(v.x), "=f"(v.y), "=f"(v.z), "=f"(v.w)
                 : "r"(smem_u32(p)));
    return v;
}

// ---------------------------------------------------------------------------
// prepN (32x32 tiles), unchanged.
// ---------------------------------------------------------------------------
__global__ __launch_bounds__(256)
void prepN_kernel(const float* __restrict__ W0, const float* __restrict__ W1,
                  float* __restrict__ Nmat)
{
    const int z = blockIdx.z;
    const int hp = z >> 2, h = z & 3;
    const float* A = W0 + h * 128;
    const float* B = W1 + (size_t)(h * 128) * 512 + hp * 128;
    float* C = Nmat + (size_t)hp * 65536 + (size_t)(h * 128) * 128;

    const int M0 = blockIdx.y * 32;
    const int N0 = blockIdx.x * 32;
    const int tx = threadIdx.x & 15;
    const int ty = threadIdx.x >> 4;
    const int tid = threadIdx.x;

    __shared__ float As[16][32];
    __shared__ float Bs[16][32];

    float acc[2][2] = {{0.f, 0.f}, {0.f, 0.f}};

    for (int k0 = 0; k0 < 128; k0 += 16) {
        if (tid < 128) {
            int r = tid >> 2, c4 = (tid & 3) * 4;
            float4 av = *(const float4*)(A + (size_t)(M0 + r) * 512 + k0 + c4);
            As[c4 + 0][r] = av.x;
            As[c4 + 1][r] = av.y;
            As[c4 + 2][r] = av.z;
            As[c4 + 3][r] = av.w;
        } else {
            int t = tid - 128;
            int r = t >> 3, c4 = (t & 7) * 4;
            float4 bv = *(const float4*)(B + (size_t)(k0 + r) * 512 + N0 + c4);
            *(float4*)&Bs[r][c4] = bv;
        }
        __syncthreads();
        #pragma unroll
        for (int k = 0; k < 16; k++) {
            float a0 = As[k][ty * 2], a1 = As[k][ty * 2 + 1];
            float b0 = Bs[k][tx * 2], b1 = Bs[k][tx * 2 + 1];
            acc[0][0] = fmaf(a0, b0, acc[0][0]);
            acc[0][1] = fmaf(a0, b1, acc[0][1]);
            acc[1][0] = fmaf(a1, b0, acc[1][0]);
            acc[1][1] = fmaf(a1, b1, acc[1][1]);
        }
        __syncthreads();
    }
    #pragma unroll
    for (int i = 0; i < 2; i++)
        #pragma unroll
        for (int j = 0; j < 2; j++)
            C[(size_t)(M0 + ty * 2 + i) * 128 + N0 + tx * 2 + j] = acc[i][j];
}

// ---------------------------------------------------------------------------
// prepQP, unchanged.
// ---------------------------------------------------------------------------
__global__ __launch_bounds__(128)
void prepQP_kernel(const float* __restrict__ Nmat,
                   const float* __restrict__ a1s, const float* __restrict__ a1n,
                   const float* __restrict__ W0,
                   const float* __restrict__ a0s, const float* __restrict__ a0n,
                   float* __restrict__ Q, float* __restrict__ P0)
{
    const int b = blockIdx.x;
    const int tid = threadIdx.x;
    if (b < 16) {
        const int hp = b >> 2, h = b & 3;
        __shared__ float sa1s[128], sa1n[128];
        sa1s[tid] = a1s[hp * 128 + tid];
        sa1n[tid] = a1n[hp * 128 + tid];
        __syncthreads();
        const float* nrow = Nmat + (size_t)hp * 65536 + (size_t)(h * 128 + tid) * 128;
        float s = 0.f, n = 0.f;
        #pragma unroll 4
        for (int d = 0; d < 128; d++) {
            float nv = nrow[d];
            s = fmaf(nv, sa1s[d], s);
            n = fmaf(nv, sa1n[d], n);
        }
        Q[hp * 512 + h * 128 + tid] = s;
        Q[2048 + hp * 512 + h * 128 + tid] = n;
    } else {
        const int t = (b - 16) * 128 + tid;
        const int h = t >> 7, f = t & 127;
        const float* wrow = W0 + (size_t)f * 512 + h * 128;
        const float* as = a0s + h * 128;
        const float* an = a0n + h * 128;
        float s = 0.f, n = 0.f;
        #pragma unroll 4
        for (int d = 0; d < 128; d++) {
            float wv = wrow[d];
            s = fmaf(wv, as[d], s);
            n = fmaf(wv, an[d], n);
        }
        P0[t] = s;
        P0[512 + t] = n;
    }
}

// ---------------------------------------------------------------------------
// fp32 GEMM: 64x64 tile, BK=16, 256 threads, 4x4/thread, reg double-buffer.
// ---------------------------------------------------------------------------
__global__ __launch_bounds__(256)
void gemm_kernel(const float* __restrict__ A, const float* __restrict__ B,
                 float* __restrict__ C,
                 int K, int lda, int ldb, int ldc,
                 int offA, int offB, int offC)
{
    A += (size_t)blockIdx.z * offA;
    B += (size_t)blockIdx.z * offB;
    C += (size_t)blockIdx.z * offC;

    const int row0 = blockIdx.y * 64;
    const int col0 = blockIdx.x * 64;
    const int tx = threadIdx.x;
    const int ty = threadIdx.y;
    const int tid = ty * 16 + tx;

    __shared__ float As[16][64];
    __shared__ float Bs[16][64];

    const int ar = tid >> 2;
    const int ac = (tid & 3) * 4;
    const int br = tid >> 4;
    const int bc = (tid & 15) * 4;

    float acc[4][4];
    #pragma unroll
    for (int i = 0; i < 4; i++)
        #pragma unroll
        for (int j = 0; j < 4; j++) acc[i][j] = 0.f;

    const int nt = K >> 4;
    float4 av = *(const float4*)(A + (size_t)(row0 + ar) * lda + ac);
    float4 bv = *(const float4*)(B + (size_t)br * ldb + col0 + bc);

    for (int i = 0; i < nt; i++) {
        As[ac + 0][ar] = av.x;
        As[ac + 1][ar] = av.y;
        As[ac + 2][ar] = av.z;
        As[ac + 3][ar] = av.w;
        *(float4*)&Bs[br][bc] = bv;
        __syncthreads();

        if (i + 1 < nt) {
            int k0 = (i + 1) << 4;
            av = *(const float4*)(A + (size_t)(row0 + ar) * lda + k0 + ac);
            bv = *(const float4*)(B + (size_t)(k0 + br) * ldb + col0 + bc);
        }

        #pragma unroll
        for (int k = 0; k < 16; k++) {
            float4 a4 = *(const float4*)&As[k][ty * 4];
            float4 b4 = *(const float4*)&Bs[k][tx * 4];
            float a[4] = {a4.x, a4.y, a4.z, a4.w};
            float b[4] = {b4.x, b4.y, b4.z, b4.w};
            #pragma unroll
            for (int ii = 0; ii < 4; ii++)
                #pragma unroll
                for (int jj = 0; jj < 4; jj++)
                    acc[ii][jj] = fmaf(a[ii], b[jj], acc[ii][jj]);
        }
        __syncthreads();
    }

    #pragma unroll
    for (int i = 0; i < 4; i++) {
        float4 o = {acc[i][0], acc[i][1], acc[i][2], acc[i][3]};
        *(float4*)(C + (size_t)(row0 + ty * 4 + i) * ldc + col0 + tx * 4) = o;
    }
}

// ---------------------------------------------------------------------------
// F=128 attention body, compile-time E (full unrolling / LDS MLP).
// ---------------------------------------------------------------------------
template<int E>
static __device__ __forceinline__ void attn128_body(
    const float* __restrict__ gxn, const float* __restrict__ gxs,
    float* __restrict__ gy, float* __restrict__ eout,
    const float* __restrict__ Ws, const float* __restrict__ Wn,
    const float* __restrict__ qb,
    float* sxn, float* slog, float* salpha, float (*sred)[4], uint32_t mbar)
{
    const int tid  = threadIdx.x;
    const int w    = tid >> 5;
    const int lane = tid & 31;
    const int hh   = lane & 3;
    const int s    = lane >> 2;

    if (tid == 0) {
        mbar_expect_tx(mbar, (uint32_t)(E * 128 * 4));
        bulk_g2s(smem_u32(sxn), gxn, (uint32_t)(E * 128 * 4), mbar);
    }

    float4 wq[4];
    #pragma unroll
    for (int j = 0; j < 4; j++) wq[j] = ldg4(Wn + hh * 128 + 4 * (s + 8 * j));

    // layer-1 weight slice for the elog side-output
    float qv[4][4];
    #pragma unroll
    for (int hp = 0; hp < 4; hp++)
        #pragma unroll
        for (int q = 0; q < 4; q++)
            qv[hp][q] = __ldg(qb + hp * 512 + q * 128 + tid);

    if (w == 0) {  // self logit from global
        float acc = 0.f;
        #pragma unroll
        for (int j = 0; j < 4; j++)
            acc = dot4(ldg4(gxs + 4 * (s + 8 * j)),
                       ldg4(Ws + hh * 128 + 4 * (s + 8 * j)), acc);
        acc += __shfl_xor_sync(0xffffffffu, acc, 4);
        acc += __shfl_xor_sync(0xffffffffu, acc, 8);
        acc += __shfl_xor_sync(0xffffffffu, acc, 16);
        if (lane < 4) slog[E * 4 + lane] = acc;
    }

    mbar_wait(mbar, 0);

    // neighbor logits: warp w handles e = w, w+4, ... (unrolled, independent)
    #pragma unroll
    for (int eb = 0; eb < (E + 3) / 4; eb++) {
        int e = eb * 4 + w;
        if (e < E) {
            const float* xp = &sxn[e * 128];
            float acc = 0.f;
            #pragma unroll
            for (int j = 0; j < 4; j++)
                acc = dot4(lds4(xp + 4 * (s + 8 * j)), wq[j], acc);
            acc += __shfl_xor_sync(0xffffffffu, acc, 4);
            acc += __shfl_xor_sync(0xffffffffu, acc, 8);
            acc += __shfl_xor_sync(0xffffffffu, acc, 16);
            if (lane < 4) slog[e * 4 + lane] = acc;
        }
    }
    __syncthreads();

    {   // softmax per head (warp w = head)
        float es = slog[E * 4 + w];
        float v;
        if (lane < E) {
            float l = es + slog[lane * 4 + w];
            v = (l >= 0.f) ? l : 0.2f * l;
        } else {
            v = -3.4e38f;
        }
        float m = v;
        #pragma unroll
        for (int o = 16; o; o >>= 1) m = fmaxf(m, __shfl_xor_sync(0xffffffffu, m, o));
        float p = (lane < E) ? __expf(v - m) : 0.f;
        float sum = p;
        #pragma unroll
        for (int o = 16; o; o >>= 1) sum += __shfl_xor_sync(0xffffffffu, sum, o);
        if (lane < E) salpha[lane * 4 + w] = p / sum;
    }
    __syncthreads();

    // aggregate (fully unrolled -> E independent LDS in flight)
    float acc[4] = {0.f, 0.f, 0.f, 0.f};
    #pragma unroll
    for (int e = 0; e < E; e++) {
        float val = sxn[e * 128 + tid];
        #pragma unroll
        for (int q = 0; q < 4; q++) acc[q] = fmaf(salpha[e * 4 + q], val, acc[q]);
    }
    #pragma unroll
    for (int q = 0; q < 4; q++) gy[q * 128 + tid] = acc[q];

    // fused layer-1 logit partials: p[hp] = sum_f y[f] * Q[hp][f]
    float p[4];
    #pragma unroll
    for (int hp = 0; hp < 4; hp++) {
        float t = 0.f;
        #pragma unroll
        for (int q = 0; q < 4; q++) t = fmaf(acc[q], qv[hp][q], t);
        #pragma unroll
        for (int o = 16; o; o >>= 1) t += __shfl_xor_sync(0xffffffffu, t, o);
        p[hp] = t;
    }
    if (lane == 0) {
        #pragma unroll
        for (int hp = 0; hp < 4; hp++) sred[w][hp] = p[hp];
    }
    __syncthreads();
    if (tid < 4)
        eout[tid] = sred[0][tid] + sred[1][tid] + sred[2][tid] + sred[3][tid];
}

__global__ __launch_bounds__(128)
void attn128_kernel(const float* __restrict__ h0, const float* __restrict__ h1,
                    const float* __restrict__ h2,
                    const float* __restrict__ Ws, const float* __restrict__ Wn,
                    const float* __restrict__ Q,
                    float* __restrict__ y1, float* __restrict__ y0,
                    float* __restrict__ elogN, float* __restrict__ elogS, int G1)
{
    __shared__ float sxn[25 * 128];
    __shared__ float slog[26 * 4];
    __shared__ float salpha[25 * 4];
    __shared__ float sred[4][4];
    __shared__ uint64_t mbar_s;

    const int b = blockIdx.x;
    const uint32_t mbar = smem_u32(&mbar_s);
    if (threadIdx.x == 0) {
        mbar_init(mbar, 1);
        asm volatile("fence.proxy.async.shared::cta;" ::: "memory");
    }
    __syncthreads();

    if (b < G1) {
        attn128_body<25>(h2 + (size_t)b * 25 * 128, h1 + (size_t)b * 128,
                         y1 + (size_t)b * 512, elogN + (size_t)b * 4,
                         Ws, Wn, Q + 2048, sxn, slog, salpha, sred, mbar);
    } else {
        const int g = b - G1;
        attn128_body<10>(h1 + (size_t)g * 10 * 128, h0 + (size_t)g * 128,
                         y0 + (size_t)g * 512, elogS + (size_t)g * 4,
                         Ws, Wn, Q, sxn, slog, salpha, sred, mbar);
    }
}

// ---------------------------------------------------------------------------
// F=512, E=10 layer-1: logits precomputed; TMA + softmax + aggregate only.
// ---------------------------------------------------------------------------
__global__ __launch_bounds__(128)
void attn512_kernel(const float* __restrict__ xn,
                    const float* __restrict__ elogS, const float* __restrict__ elogN,
                    float* __restrict__ y)
{
    constexpr int E = 10, F = 512;
    __shared__ float sxn[E * F];
    __shared__ float salpha[E * 4];
    __shared__ uint64_t mbar_s;

    const int g    = blockIdx.x;
    const int tid  = threadIdx.x;
    const int w    = tid >> 5;
    const int lane = tid & 31;
    const uint32_t mbar = smem_u32(&mbar_s);
    const float* gxn = xn + (size_t)g * E * F;

    if (tid == 0) {
        mbar_init(mbar, 1);
        asm volatile("fence.proxy.async.shared::cta;" ::: "memory");
    }
    __syncthreads();
    if (tid == 0) {
        mbar_expect_tx(mbar, E * F * 4);
        bulk_g2s(smem_u32(sxn), gxn, E * F * 4, mbar);
    }

    {   // softmax per head from precomputed logits
        float es = __ldg(elogS + g * 4 + w);
        float v;
        if (lane < E) {
            float l = es + __ldg(elogN + (size_t)(g * 10 + lane) * 4 + w);
            v = (l >= 0.f) ? l : 0.2f * l;
        } else {
            v = -3.4e38f;
        }
        float m = v;
        #pragma unroll
        for (int o = 16; o; o >>= 1) m = fmaxf(m, __shfl_xor_sync(0xffffffffu, m, o));
        float p = (lane < E) ? __expf(v - m) : 0.f;
        float sum = p;
        #pragma unroll
        for (int o = 16; o; o >>= 1) sum += __shfl_xor_sync(0xffffffffu, sum, o);
        if (lane < E) salpha[lane * 4 + w] = p / sum;
    }

    mbar_wait(mbar, 0);
    __syncthreads();

    float acc[4][4];
    #pragma unroll
    for (int c = 0; c < 4; c++)
        #pragma unroll
        for (int q = 0; q < 4; q++) acc[c][q] = 0.f;
    #pragma unroll
    for (int e = 0; e < E; e++) {
        float al[4];
        #pragma unroll
        for (int q = 0; q < 4; q++) al[q] = salpha[e * 4 + q];
        #pragma unroll
        for (int c = 0; c < 4; c++) {
            float val = sxn[e * F + c * 128 + tid];
            #pragma unroll
            for (int q = 0; q < 4; q++) acc[c][q] = fmaf(al[q], val, acc[c][q]);
        }
    }
    float* gy = y + (size_t)g * (4 * F);
    #pragma unroll
    for (int q = 0; q < 4; q++)
        #pragma unroll
        for (int c = 0; c < 4; c++)
            gy[q * F + c * 128 + tid] = acc[c][q];
}

// ---------------------------------------------------------------------------
extern "C" void kernel_launch(void* const* d_in, const int* in_sizes, int n_in,
                              void* d_out, int out_size)
{
    const float* h0  = (const float*)d_in[0];
    const float* h1  = (const float*)d_in[1];
    const float* h2  = (const float*)d_in[2];
    const float* W0  = (const float*)d_in[3];
    const float* a0s = (const float*)d_in[4];
    const float* a0n = (const float*)d_in[5];
    const float* W1  = (const float*)d_in[6];
    const float* a1s = (const float*)d_in[7];
    const float* a1n = (const float*)d_in[8];
    const float* Wfc = (const float*)d_in[9];
    float* out = (float*)d_out;

    float* scr = nullptr;
    cudaGetSymbolAddress((void**)&scr, g_scratch);
    float* y1    = scr + OFF_Y1;
    float* y0    = scr + OFF_Y0;
    float* u     = scr + OFF_U;
    float* hs0   = scr + OFF_H;
    float* P0    = scr + OFF_P0;
    float* Q     = scr + OFF_Q;
    float* Nmat  = scr + OFF_N;
    float* elogN = scr + OFF_EN;
    float* elogS = scr + OFF_ES;

    prepN_kernel<<<dim3(4, 4, 16), 256>>>(W0, W1, Nmat);
    prepQP_kernel<<<20, 128>>>(Nmat, a1s, a1n, W0, a0s, a0n, Q, P0);

    // both F=128 attentions + fused layer-1 logits
    attn128_kernel<<<10240 + 1024, 128>>>(h0, h1, h2, P0, P0 + 512, Q,
                                          y1, y0, elogN, elogS, 10240);

    // layer-1 softmax + aggregation only
    attn512_kernel<<<1024, 128>>>(y1, elogS, elogN, u);

    // hs0[g, hp*128+d'] = u[g,hp,:] @ N[hp]
    gemm_kernel<<<dim3(2, 16, 4), dim3(16, 16)>>>(u, Nmat, hs0, 512, 2048, 128, 512,
                                                  512, 512 * 128, 128);
    // out = hs0 @ Wfc
    gemm_kernel<<<dim3(4, 16, 1), dim3(16, 16)>>>(hs0, Wfc, out, 512, 512, 256, 256,
                                                  0, 0, 0);
}